// round 14
// baseline (speedup 1.0000x reference)
#include <cuda_runtime.h>
#include <cuda_fp16.h>
#include <math.h>
#include <stdint.h>

#define DMODEL 1024
#define NHEADS 16
#define DHEAD  64
#define TSEQ   2048
#define MMAX   4096   // B*T

// ---------------- device scratch (allocation-free) ----------------
__device__ __half g_Qh[MMAX * DMODEL];
__device__ __half g_Kh[MMAX * DMODEL];
__device__ __half g_Vh[MMAX * DMODEL];
__device__ __half g_xh[MMAX * DMODEL];
__device__ __half g_wh[4 * DMODEL * DMODEL];
__device__ __half g_ah[MMAX * DMODEL];

// ---------------- helpers ----------------
__device__ __forceinline__ void mma_f16(
    float& c0, float& c1, float& c2, float& c3,
    unsigned a0, unsigned a1, unsigned a2, unsigned a3,
    unsigned b0, unsigned b1)
{
    asm volatile(
        "mma.sync.aligned.m16n8k16.row.col.f32.f16.f16.f32 "
        "{%0,%1,%2,%3}, {%4,%5,%6,%7}, {%8,%9}, {%0,%1,%2,%3};\n"
        : "+f"(c0), "+f"(c1), "+f"(c2), "+f"(c3)
        : "r"(a0), "r"(a1), "r"(a2), "r"(a3), "r"(b0), "r"(b1));
}

__device__ __forceinline__ void ldsm_x4(
    unsigned& r0, unsigned& r1, unsigned& r2, unsigned& r3, uint32_t addr)
{
    asm volatile("ldmatrix.sync.aligned.m8n8.x4.shared.b16 {%0,%1,%2,%3}, [%4];"
                 : "=r"(r0), "=r"(r1), "=r"(r2), "=r"(r3) : "r"(addr));
}

__device__ __forceinline__ void ldsm_x4_t(
    unsigned& r0, unsigned& r1, unsigned& r2, unsigned& r3, uint32_t addr)
{
    asm volatile("ldmatrix.sync.aligned.m8n8.x4.trans.shared.b16 {%0,%1,%2,%3}, [%4];"
                 : "=r"(r0), "=r"(r1), "=r"(r2), "=r"(r3) : "r"(addr));
}

__device__ __forceinline__ float fexp2(float x) {
    float r;
    asm("ex2.approx.ftz.f32 %0, %1;" : "=f"(r) : "f"(x));
    return r;
}

__device__ __forceinline__ uint32_t smem_u32(const void* p) {
    uint32_t a;
    asm("{ .reg .u64 t; cvta.to.shared.u64 t, %1; cvt.u32.u64 %0, t; }"
        : "=r"(a) : "l"(p));
    return a;
}

__device__ __forceinline__ void cp16(uint32_t dst, const void* src) {
    asm volatile("cp.async.cg.shared.global [%0], [%1], 16;"
                 :: "r"(dst), "l"(src) : "memory");
}
__device__ __forceinline__ void cp_commit() {
    asm volatile("cp.async.commit_group;" ::: "memory");
}
template<int N> __device__ __forceinline__ void cp_wait() {
    asm volatile("cp.async.wait_group %0;" :: "n"(N) : "memory");
}

// ---------------------------------------------------------------------------
// Elementwise converts
// ---------------------------------------------------------------------------
__global__ __launch_bounds__(256) void tohalf_kernel(
    const float* __restrict__ in, __half* __restrict__ out, int n4)
{
    int i = blockIdx.x * blockDim.x + threadIdx.x;
    if (i >= n4) return;
    float4 v = ((const float4*)in)[i];
    __half2 a = __floats2half2_rn(v.x, v.y);
    __half2 b = __floats2half2_rn(v.z, v.w);
    ((uint2*)out)[i] = make_uint2(*reinterpret_cast<unsigned*>(&a),
                                  *reinterpret_cast<unsigned*>(&b));
}

// All four weights in one launch (blockIdx.y selects).
__global__ __launch_bounds__(256) void tohalf4_kernel(
    const float* __restrict__ w0, const float* __restrict__ w1,
    const float* __restrict__ w2, const float* __restrict__ w3,
    __half* __restrict__ out, int n4)
{
    const float* srcs[4] = {w0, w1, w2, w3};
    const float* in = srcs[blockIdx.y];
    __half* o = out + (size_t)blockIdx.y * DMODEL * DMODEL;
    int i = blockIdx.x * blockDim.x + threadIdx.x;
    if (i >= n4) return;
    float4 v = ((const float4*)in)[i];
    __half2 a = __floats2half2_rn(v.x, v.y);
    __half2 b = __floats2half2_rn(v.z, v.w);
    ((uint2*)o)[i] = make_uint2(*reinterpret_cast<unsigned*>(&a),
                                *reinterpret_cast<unsigned*>(&b));
}

// ---------------------------------------------------------------------------
// Single-term fp16 GEMM: C = Ah @ Wh^T + bias (f32 accum).
// BM=128, BN=128, BK=32, 256 threads = 8 warps (4Mx2N), warp tile 32x64.
// Multi-output: bn_global >> 10 selects out/bias/scale (QKV fused launch).
// ---------------------------------------------------------------------------
#define GBM 128
#define GBN 128
#define GBK 32
#define GST 20
#define TILE_U32 (128 * GST)
#define STAGE_U32 (2 * TILE_U32)      // Ah, Bh
#define GEMM_SMEM (2 * STAGE_U32 * 4)
#define NT (DMODEL / GBK)

struct GemmOuts {
    void* out[3];
    const float* bias[3];
    float scale[3];
};

__device__ __forceinline__ void gemm_copy_stage(
    uint32_t sbase, const __half* Ah, const __half* Bh,
    int bm, int bnG, int k0, int tid)
{
    const __half* srcs[2] = {Ah, Bh};
    #pragma unroll
    for (int t = 0; t < 2; t++) {
        const int rbase = (t == 0) ? bm : bnG;
        const uint32_t toff = sbase + t * TILE_U32 * 4;
        #pragma unroll
        for (int i = 0; i < 2; i++) {
            const int c   = tid + i * 256;
            const int row = c >> 2;
            const int kc  = c & 3;
            cp16(toff + (row * GST + kc * 4) * 4,
                 srcs[t] + (size_t)(rbase + row) * DMODEL + k0 + kc * 8);
        }
    }
}

template<int OUTH>
__global__ __launch_bounds__(256) void gemm_f16_kernel(
    const __half* __restrict__ Ah, const __half* __restrict__ Bh, GemmOuts go)
{
    extern __shared__ unsigned gsm[];
    const uint32_t sb = smem_u32(gsm);

    const int tid  = threadIdx.x;
    const int lane = tid & 31;
    const int warp = tid >> 5;
    const int wm   = warp >> 1;
    const int wn   = warp & 1;
    const int lr   = lane >> 2;
    const int lc   = lane & 3;

    const int bm  = blockIdx.y * GBM;
    const int bnG = blockIdx.x * GBN;
    const int buf = bnG >> 10;
    const int bn  = bnG & 1023;

    float acc[2][8][4] = {};

    gemm_copy_stage(sb, Ah, Bh, bm, bnG, 0, tid);
    cp_commit();

    for (int kt = 0; kt < NT; kt++) {
        const int cur = kt & 1;
        if (kt + 1 < NT) {
            gemm_copy_stage(sb + ((kt + 1) & 1) * STAGE_U32 * 4,
                            Ah, Bh, bm, bnG, (kt + 1) * GBK, tid);
            cp_commit();
            cp_wait<1>();
        } else {
            cp_wait<0>();
        }
        __syncthreads();

        const unsigned* As = gsm + cur * STAGE_U32;
        const unsigned* Bs = As + TILE_U32;

        #pragma unroll
        for (int ks = 0; ks < 2; ks++) {
            const int k = ks * 8;
            unsigned ah[2][4], bh[8][2];
            #pragma unroll
            for (int mi = 0; mi < 2; mi++) {
                const int r0 = (wm * 32 + mi * 16 + lr) * GST;
                ah[mi][0] = As[r0 + k + lc];
                ah[mi][1] = As[r0 + 8 * GST + k + lc];
                ah[mi][2] = As[r0 + k + lc + 4];
                ah[mi][3] = As[r0 + 8 * GST + k + lc + 4];
            }
            #pragma unroll
            for (int ni = 0; ni < 8; ni++) {
                const int n0 = (wn * 64 + ni * 8 + lr) * GST;
                bh[ni][0] = Bs[n0 + k + lc];
                bh[ni][1] = Bs[n0 + k + lc + 4];
            }
            #pragma unroll
            for (int mi = 0; mi < 2; mi++)
                #pragma unroll
                for (int ni = 0; ni < 8; ni++)
                    mma_f16(acc[mi][ni][0], acc[mi][ni][1],
                            acc[mi][ni][2], acc[mi][ni][3],
                            ah[mi][0], ah[mi][1], ah[mi][2], ah[mi][3],
                            bh[ni][0], bh[ni][1]);
        }
        __syncthreads();
    }

    const float* bias = go.bias[buf];
    const float oscale = go.scale[buf];

    #pragma unroll
    for (int mi = 0; mi < 2; mi++) {
        #pragma unroll
        for (int ni = 0; ni < 8; ni++) {
            const int r = bm + wm * 32 + mi * 16 + lr;
            const int c = bn + wn * 64 + ni * 8 + lc * 2;
            float2 b0 = *(const float2*)(bias + c);
            float v0 = acc[mi][ni][0] + b0.x, v1 = acc[mi][ni][1] + b0.y;
            float v2 = acc[mi][ni][2] + b0.x, v3 = acc[mi][ni][3] + b0.y;
            if (OUTH) {
                __half* C = (__half*)go.out[buf];
                *(__half2*)(C + (size_t)r * DMODEL + c) =
                    __floats2half2_rn(v0 * oscale, v1 * oscale);
                *(__half2*)(C + (size_t)(r + 8) * DMODEL + c) =
                    __floats2half2_rn(v2 * oscale, v3 * oscale);
            } else {
                float* C = (float*)go.out[buf];
                *(float2*)(C + (size_t)r * DMODEL + c)       = make_float2(v0, v1);
                *(float2*)(C + (size_t)(r + 8) * DMODEL + c) = make_float2(v2, v3);
            }
        }
    }
}

// ---------------------------------------------------------------------------
// fp16 flash attention (causal): 128 q-rows/block, 8 warps (16 rows each),
// 64-key tiles, ldmatrix + 3-stage cp.async ring, exp2-domain softmax.
// Q arrives pre-scaled by log2(e)/8.
// ---------------------------------------------------------------------------
#define RS 72
#define ABM 128
#define KTILE_H (64 * RS)                               // halves per K/V tile
#define QTILE_H (ABM * RS)                              // halves for Q / P
#define ATT_SMEM ((2 * QTILE_H + 6 * KTILE_H) * 2)      // 90 KB

__device__ __forceinline__ void att_copy_kv(
    uint32_t kdst, uint32_t vdst,
    const __half* Kp, const __half* Vp, int kt, int tid)
{
    #pragma unroll
    for (int j = 0; j < 2; j++) {
        const int i   = tid + j * 256;
        const int row = i >> 3;
        const int c8  = (i & 7) * 8;
        const size_t g = (size_t)(kt * 64 + row) * DMODEL + c8;
        cp16(kdst + (row * RS + c8) * 2, Kp + g);
        cp16(vdst + (row * RS + c8) * 2, Vp + g);
    }
}

__global__ __launch_bounds__(256) void flash_attn_h_kernel(
    const __half* __restrict__ Q, const __half* __restrict__ K,
    const __half* __restrict__ V, __half* __restrict__ Oh, int T)
{
    extern __shared__ __half hsm[];
    __half* Qs = hsm;
    __half* Ps = Qs + QTILE_H;
    __half* Ks = Ps + QTILE_H;            // 3 tiles
    __half* Vs = Ks + 3 * KTILE_H;        // 3 tiles

    const int tid  = threadIdx.x;
    const int lane = tid & 31;
    const int warp = tid >> 5;            // 0..7 -> q rows warp*16..+15
    const int lr   = lane >> 2;
    const int lc   = lane & 3;
    const int qt   = blockIdx.x;          // 128-row q tile
    const int h    = blockIdx.y;
    const int bb   = blockIdx.z;

    const size_t base = ((size_t)bb * T) * DMODEL + h * DHEAD;
    const __half* Qp = Q + base;
    const __half* Kp = K + base;
    const __half* Vp = V + base;

    const uint32_t qb = smem_u32(Qs);
    const uint32_t kb = smem_u32(Ks);
    const uint32_t vb = smem_u32(Vs);
    const uint32_t pb = smem_u32(Ps);

    const int sel = lane >> 3, l7 = lane & 7;
    const uint32_t a_off = (((uint32_t)(warp * 16 + l7 + (sel & 1) * 8)) * RS
                            + (sel >> 1) * 8) * 2;
    const uint32_t kb_off = (((uint32_t)((sel >> 1) * 8 + l7)) * RS + (sel & 1) * 8) * 2;
    const uint32_t vb_off = (((uint32_t)((sel & 1) * 8 + l7)) * RS + (sel >> 1) * 8) * 2;

    const int nkt = 2 * qt + 2;                 // 64-key tiles to visit
    const int rowbase = qt * ABM + warp * 16;   // this warp's first q row
    const int rowmax  = rowbase + 15;

    // Prologue: prefetch tiles 0 and 1 (always two commit groups)
    att_copy_kv(kb, vb, Kp, Vp, 0, tid);
    cp_commit();
    if (nkt > 1)
        att_copy_kv(kb + KTILE_H * 2, vb + KTILE_H * 2, Kp, Vp, 1, tid);
    cp_commit();

    // Load Q tile (fp16, pre-scaled by log2e/8 at projection)
    #pragma unroll
    for (int j = 0; j < 4; j++) {
        const int i   = tid + j * 256;
        const int row = i >> 3;
        const int c8  = (i & 7) * 8;
        *(uint4*)(Qs + row * RS + c8) =
            *(const uint4*)(Qp + (size_t)(qt * ABM + row) * DMODEL + c8);
    }

    float m0 = -INFINITY, m1 = -INFINITY, l0 = 0.f, l1 = 0.f;
    float o[8][4] = {};

    for (int kt = 0; kt < nkt; kt++) {
        cp_wait<1>();
        __syncthreads();

        if (kt + 2 < nkt) {
            const int s2 = (kt + 2) % 3;
            att_copy_kv(kb + s2 * KTILE_H * 2, vb + s2 * KTILE_H * 2,
                        Kp, Vp, kt + 2, tid);
        }
        cp_commit();

        // Warp-uniform skip: this k-tile entirely above this warp's rows.
        if (kt * 64 <= rowmax) {
            const uint32_t kcur = kb + (kt % 3) * KTILE_H * 2;
            const uint32_t vcur = vb + (kt % 3) * KTILE_H * 2;

            // S = Q K^T
            float s[8][4] = {};
            #pragma unroll
            for (int ks = 0; ks < 4; ks++) {
                unsigned a0, a1, a2, a3;
                ldsm_x4(a0, a1, a2, a3, qb + a_off + ks * 32);
                #pragma unroll
                for (int np = 0; np < 4; np++) {
                    unsigned b0, b1, b2, b3;
                    ldsm_x4(b0, b1, b2, b3,
                            kcur + kb_off + ((np * 16) * RS + ks * 16) * 2);
                    mma_f16(s[2 * np][0], s[2 * np][1], s[2 * np][2], s[2 * np][3],
                            a0, a1, a2, a3, b0, b1);
                    mma_f16(s[2 * np + 1][0], s[2 * np + 1][1],
                            s[2 * np + 1][2], s[2 * np + 1][3],
                            a0, a1, a2, a3, b2, b3);
                }
            }

            // Causal mask on diagonal-straddling tiles (global indices)
            if (kt * 64 + 63 > rowbase) {
                #pragma unroll
                for (int nt = 0; nt < 8; nt++) {
                    const int col = kt * 64 + nt * 8 + 2 * lc;
                    const int r0g = rowbase + lr;
                    if (col     > r0g)     s[nt][0] = -INFINITY;
                    if (col + 1 > r0g)     s[nt][1] = -INFINITY;
                    if (col     > r0g + 8) s[nt][2] = -INFINITY;
                    if (col + 1 > r0g + 8) s[nt][3] = -INFINITY;
                }
            }

            // Online softmax in exp2 domain
            float mt0 = -INFINITY, mt1 = -INFINITY;
            #pragma unroll
            for (int nt = 0; nt < 8; nt++) {
                mt0 = fmaxf(mt0, fmaxf(s[nt][0], s[nt][1]));
                mt1 = fmaxf(mt1, fmaxf(s[nt][2], s[nt][3]));
            }
            #pragma unroll
            for (int off = 1; off <= 2; off <<= 1) {
                mt0 = fmaxf(mt0, __shfl_xor_sync(0xffffffffu, mt0, off));
                mt1 = fmaxf(mt1, __shfl_xor_sync(0xffffffffu, mt1, off));
            }
            const float mn0 = fmaxf(m0, mt0), mn1 = fmaxf(m1, mt1);
            const float corr0 = fexp2(m0 - mn0), corr1 = fexp2(m1 - mn1);
            float ls0 = 0.f, ls1 = 0.f;
            #pragma unroll
            for (int nt = 0; nt < 8; nt++) {
                s[nt][0] = fexp2(s[nt][0] - mn0);
                s[nt][1] = fexp2(s[nt][1] - mn0);
                s[nt][2] = fexp2(s[nt][2] - mn1);
                s[nt][3] = fexp2(s[nt][3] - mn1);
                ls0 += s[nt][0] + s[nt][1];
                ls1 += s[nt][2] + s[nt][3];
            }
            #pragma unroll
            for (int off = 1; off <= 2; off <<= 1) {
                ls0 += __shfl_xor_sync(0xffffffffu, ls0, off);
                ls1 += __shfl_xor_sync(0xffffffffu, ls1, off);
            }
            l0 = l0 * corr0 + ls0;  m0 = mn0;
            l1 = l1 * corr1 + ls1;  m1 = mn1;

            {
                const uint32_t pr0 = (uint32_t)(warp * 16 + lr) * RS + 2 * lc;
                #pragma unroll
                for (int nt = 0; nt < 8; nt++) {
                    o[nt][0] *= corr0; o[nt][1] *= corr0;
                    o[nt][2] *= corr1; o[nt][3] *= corr1;
                    *(__half2*)(Ps + pr0 + nt * 8) =
                        __floats2half2_rn(s[nt][0], s[nt][1]);
                    *(__half2*)(Ps + pr0 + 8 * RS + nt * 8) =
                        __floats2half2_rn(s[nt][2], s[nt][3]);
                }
            }
            __syncwarp();

            // O += P V
            #pragma unroll
            for (int ks = 0; ks < 4; ks++) {
                unsigned a0, a1, a2, a3;
                ldsm_x4(a0, a1, a2, a3, pb + a_off + ks * 32);
                #pragma unroll
                for (int np = 0; np < 4; np++) {
                    unsigned b0, b1, b2, b3;
                    ldsm_x4_t(b0, b1, b2, b3,
                              vcur + vb_off + ((ks * 16) * RS + np * 16) * 2);
                    mma_f16(o[2 * np][0], o[2 * np][1], o[2 * np][2], o[2 * np][3],
                            a0, a1, a2, a3, b0, b1);
                    mma_f16(o[2 * np + 1][0], o[2 * np + 1][1],
                            o[2 * np + 1][2], o[2 * np + 1][3],
                            a0, a1, a2, a3, b2, b3);
                }
            }
        }
        // next iteration's __syncthreads covers WAR safety
    }

    // Epilogue: normalize + store fp16
    const float inv0 = 1.0f / l0, inv1 = 1.0f / l1;
    const size_t row0 = (size_t)bb * T + qt * ABM + warp * 16 + lr;
    #pragma unroll
    for (int nt = 0; nt < 8; nt++) {
        const int col = h * DHEAD + nt * 8 + 2 * lc;
        *(__half2*)(Oh + row0 * DMODEL + col) =
            __floats2half2_rn(o[nt][0] * inv0, o[nt][1] * inv0);
        *(__half2*)(Oh + (row0 + 8) * DMODEL + col) =
            __floats2half2_rn(o[nt][2] * inv1, o[nt][3] * inv1);
    }
}

// ---------------------------------------------------------------------------
extern "C" void kernel_launch(void* const* d_in, const int* in_sizes, int n_in,
                              void* d_out, int out_size)
{
    const float* x  = (const float*)d_in[0];
    const float* Wq = (const float*)d_in[1];
    const float* bq = (const float*)d_in[2];
    const float* Wk = (const float*)d_in[3];
    const float* bk = (const float*)d_in[4];
    const float* Wv = (const float*)d_in[5];
    const float* bv = (const float*)d_in[6];
    const float* Wo = (const float*)d_in[7];
    const float* bo = (const float*)d_in[8];
    float* out = (float*)d_out;

    const int M = in_sizes[0] / DMODEL;   // B*T
    const int B = M / TSEQ;

    __half *qh, *kh, *vh, *xh, *wh, *ah;
    cudaGetSymbolAddress((void**)&qh, g_Qh);
    cudaGetSymbolAddress((void**)&kh, g_Kh);
    cudaGetSymbolAddress((void**)&vh, g_Vh);
    cudaGetSymbolAddress((void**)&xh, g_xh);
    cudaGetSymbolAddress((void**)&wh, g_wh);
    cudaGetSymbolAddress((void**)&ah, g_ah);

    static bool attr_done = false;
    if (!attr_done) {
        cudaFuncSetAttribute(gemm_f16_kernel<0>,
                             cudaFuncAttributeMaxDynamicSharedMemorySize, GEMM_SMEM);
        cudaFuncSetAttribute(gemm_f16_kernel<1>,
                             cudaFuncAttributeMaxDynamicSharedMemorySize, GEMM_SMEM);
        cudaFuncSetAttribute(flash_attn_h_kernel,
                             cudaFuncAttributeMaxDynamicSharedMemorySize, ATT_SMEM);
        attr_done = true;
    }

    // 1. converts: x -> fp16; all 4 weights -> fp16 (one launch)
    const int xn4 = M * DMODEL / 4;
    const int wn4 = DMODEL * DMODEL / 4;
    tohalf_kernel<<<(xn4 + 255) / 256, 256>>>(x, xh, xn4);
    tohalf4_kernel<<<dim3((wn4 + 255) / 256, 4), 256>>>(Wq, Wk, Wv, Wo, wh, wn4);

    // 2. fused Q/K/V projection (Q pre-scaled by log2e/8 for exp2 softmax)
    GemmOuts qkv;
    qkv.out[0] = qh;  qkv.out[1] = kh;  qkv.out[2] = vh;
    qkv.bias[0] = bq; qkv.bias[1] = bk; qkv.bias[2] = bv;
    qkv.scale[0] = 0.125f * 1.44269504f; qkv.scale[1] = 1.0f; qkv.scale[2] = 1.0f;
    dim3 qgrid(3 * DMODEL / GBN, M / GBM);
    gemm_f16_kernel<1><<<qgrid, 256, GEMM_SMEM>>>(xh, wh, qkv);

    // 3. attention (128 q-rows/block, cp.async ring; writes fp16)
    dim3 fgrid(TSEQ / ABM, NHEADS, B);
    flash_attn_h_kernel<<<fgrid, 256, ATT_SMEM>>>(qh, kh, vh, ah, TSEQ);

    // 4. output projection (fp32 epilogue)
    GemmOuts og;
    og.out[0] = out; og.out[1] = out; og.out[2] = out;
    og.bias[0] = bo; og.bias[1] = bo; og.bias[2] = bo;
    og.scale[0] = 1.0f; og.scale[1] = 1.0f; og.scale[2] = 1.0f;
    dim3 ogrid(DMODEL / GBN, M / GBM);
    gemm_f16_kernel<0><<<ogrid, 256, GEMM_SMEM>>>(
        ah, wh + 3 * (size_t)DMODEL * DMODEL, og);
}

// round 15
// speedup vs baseline: 1.0430x; 1.0430x over previous
#include <cuda_runtime.h>
#include <cuda_fp16.h>
#include <math.h>
#include <stdint.h>

#define DMODEL 1024
#define NHEADS 16
#define DHEAD  64
#define TSEQ   2048
#define MMAX   4096   // B*T

// ---------------- device scratch (allocation-free) ----------------
__device__ __half g_Qh[MMAX * DMODEL];
__device__ __half g_Kh[MMAX * DMODEL];
__device__ __half g_Vh[MMAX * DMODEL];
__device__ __half g_xh[MMAX * DMODEL];
__device__ __half g_wh[4 * DMODEL * DMODEL];
__device__ __half g_ah[MMAX * DMODEL];

// ---------------- helpers ----------------
__device__ __forceinline__ void mma_f16(
    float& c0, float& c1, float& c2, float& c3,
    unsigned a0, unsigned a1, unsigned a2, unsigned a3,
    unsigned b0, unsigned b1)
{
    asm volatile(
        "mma.sync.aligned.m16n8k16.row.col.f32.f16.f16.f32 "
        "{%0,%1,%2,%3}, {%4,%5,%6,%7}, {%8,%9}, {%0,%1,%2,%3};\n"
        : "+f"(c0), "+f"(c1), "+f"(c2), "+f"(c3)
        : "r"(a0), "r"(a1), "r"(a2), "r"(a3), "r"(b0), "r"(b1));
}

__device__ __forceinline__ void ldsm_x4(
    unsigned& r0, unsigned& r1, unsigned& r2, unsigned& r3, uint32_t addr)
{
    asm volatile("ldmatrix.sync.aligned.m8n8.x4.shared.b16 {%0,%1,%2,%3}, [%4];"
                 : "=r"(r0), "=r"(r1), "=r"(r2), "=r"(r3) : "r"(addr));
}

__device__ __forceinline__ void ldsm_x4_t(
    unsigned& r0, unsigned& r1, unsigned& r2, unsigned& r3, uint32_t addr)
{
    asm volatile("ldmatrix.sync.aligned.m8n8.x4.trans.shared.b16 {%0,%1,%2,%3}, [%4];"
                 : "=r"(r0), "=r"(r1), "=r"(r2), "=r"(r3) : "r"(addr));
}

__device__ __forceinline__ float fexp2(float x) {
    float r;
    asm("ex2.approx.ftz.f32 %0, %1;" : "=f"(r) : "f"(x));
    return r;
}

__device__ __forceinline__ uint32_t smem_u32(const void* p) {
    uint32_t a;
    asm("{ .reg .u64 t; cvta.to.shared.u64 t, %1; cvt.u32.u64 %0, t; }"
        : "=r"(a) : "l"(p));
    return a;
}

__device__ __forceinline__ void cp16(uint32_t dst, const void* src) {
    asm volatile("cp.async.cg.shared.global [%0], [%1], 16;"
                 :: "r"(dst), "l"(src) : "memory");
}
__device__ __forceinline__ void cp_commit() {
    asm volatile("cp.async.commit_group;" ::: "memory");
}
template<int N> __device__ __forceinline__ void cp_wait() {
    asm volatile("cp.async.wait_group %0;" :: "n"(N) : "memory");
}

// ---------------------------------------------------------------------------
// Elementwise converts
// ---------------------------------------------------------------------------
__global__ __launch_bounds__(256) void tohalf_kernel(
    const float* __restrict__ in, __half* __restrict__ out, int n4)
{
    int i = blockIdx.x * blockDim.x + threadIdx.x;
    if (i >= n4) return;
    float4 v = ((const float4*)in)[i];
    __half2 a = __floats2half2_rn(v.x, v.y);
    __half2 b = __floats2half2_rn(v.z, v.w);
    ((uint2*)out)[i] = make_uint2(*reinterpret_cast<unsigned*>(&a),
                                  *reinterpret_cast<unsigned*>(&b));
}

// All four weights in one launch (blockIdx.y selects).
__global__ __launch_bounds__(256) void tohalf4_kernel(
    const float* __restrict__ w0, const float* __restrict__ w1,
    const float* __restrict__ w2, const float* __restrict__ w3,
    __half* __restrict__ out, int n4)
{
    const float* srcs[4] = {w0, w1, w2, w3};
    const float* in = srcs[blockIdx.y];
    __half* o = out + (size_t)blockIdx.y * DMODEL * DMODEL;
    int i = blockIdx.x * blockDim.x + threadIdx.x;
    if (i >= n4) return;
    float4 v = ((const float4*)in)[i];
    __half2 a = __floats2half2_rn(v.x, v.y);
    __half2 b = __floats2half2_rn(v.z, v.w);
    ((uint2*)o)[i] = make_uint2(*reinterpret_cast<unsigned*>(&a),
                                *reinterpret_cast<unsigned*>(&b));
}

// ---------------------------------------------------------------------------
// Single-term fp16 GEMM: C = Ah @ Wh^T + bias (f32 accum).
// BM=128, BN=128, BK=32, 256 threads = 8 warps (4Mx2N), warp tile 32x64.
// Multi-output: bn_global >> 10 selects out/bias/scale (QKV fused launch).
// ---------------------------------------------------------------------------
#define GBM 128
#define GBN 128
#define GBK 32
#define GST 20
#define TILE_U32 (128 * GST)
#define STAGE_U32 (2 * TILE_U32)      // Ah, Bh
#define GEMM_SMEM (2 * STAGE_U32 * 4)
#define NT (DMODEL / GBK)

struct GemmOuts {
    void* out[3];
    const float* bias[3];
    float scale[3];
};

__device__ __forceinline__ void gemm_copy_stage(
    uint32_t sbase, const __half* Ah, const __half* Bh,
    int bm, int bnG, int k0, int tid)
{
    const __half* srcs[2] = {Ah, Bh};
    #pragma unroll
    for (int t = 0; t < 2; t++) {
        const int rbase = (t == 0) ? bm : bnG;
        const uint32_t toff = sbase + t * TILE_U32 * 4;
        #pragma unroll
        for (int i = 0; i < 2; i++) {
            const int c   = tid + i * 256;
            const int row = c >> 2;
            const int kc  = c & 3;
            cp16(toff + (row * GST + kc * 4) * 4,
                 srcs[t] + (size_t)(rbase + row) * DMODEL + k0 + kc * 8);
        }
    }
}

template<int OUTH>
__global__ __launch_bounds__(256) void gemm_f16_kernel(
    const __half* __restrict__ Ah, const __half* __restrict__ Bh, GemmOuts go)
{
    extern __shared__ unsigned gsm[];
    const uint32_t sb = smem_u32(gsm);

    const int tid  = threadIdx.x;
    const int lane = tid & 31;
    const int warp = tid >> 5;
    const int wm   = warp >> 1;
    const int wn   = warp & 1;
    const int lr   = lane >> 2;
    const int lc   = lane & 3;

    const int bm  = blockIdx.y * GBM;
    const int bnG = blockIdx.x * GBN;
    const int buf = bnG >> 10;
    const int bn  = bnG & 1023;

    float acc[2][8][4] = {};

    gemm_copy_stage(sb, Ah, Bh, bm, bnG, 0, tid);
    cp_commit();

    for (int kt = 0; kt < NT; kt++) {
        const int cur = kt & 1;
        if (kt + 1 < NT) {
            gemm_copy_stage(sb + ((kt + 1) & 1) * STAGE_U32 * 4,
                            Ah, Bh, bm, bnG, (kt + 1) * GBK, tid);
            cp_commit();
            cp_wait<1>();
        } else {
            cp_wait<0>();
        }
        __syncthreads();

        const unsigned* As = gsm + cur * STAGE_U32;
        const unsigned* Bs = As + TILE_U32;

        #pragma unroll
        for (int ks = 0; ks < 2; ks++) {
            const int k = ks * 8;
            unsigned ah[2][4], bh[8][2];
            #pragma unroll
            for (int mi = 0; mi < 2; mi++) {
                const int r0 = (wm * 32 + mi * 16 + lr) * GST;
                ah[mi][0] = As[r0 + k + lc];
                ah[mi][1] = As[r0 + 8 * GST + k + lc];
                ah[mi][2] = As[r0 + k + lc + 4];
                ah[mi][3] = As[r0 + 8 * GST + k + lc + 4];
            }
            #pragma unroll
            for (int ni = 0; ni < 8; ni++) {
                const int n0 = (wn * 64 + ni * 8 + lr) * GST;
                bh[ni][0] = Bs[n0 + k + lc];
                bh[ni][1] = Bs[n0 + k + lc + 4];
            }
            #pragma unroll
            for (int mi = 0; mi < 2; mi++)
                #pragma unroll
                for (int ni = 0; ni < 8; ni++)
                    mma_f16(acc[mi][ni][0], acc[mi][ni][1],
                            acc[mi][ni][2], acc[mi][ni][3],
                            ah[mi][0], ah[mi][1], ah[mi][2], ah[mi][3],
                            bh[ni][0], bh[ni][1]);
        }
        __syncthreads();
    }

    const float* bias = go.bias[buf];
    const float oscale = go.scale[buf];

    #pragma unroll
    for (int mi = 0; mi < 2; mi++) {
        #pragma unroll
        for (int ni = 0; ni < 8; ni++) {
            const int r = bm + wm * 32 + mi * 16 + lr;
            const int c = bn + wn * 64 + ni * 8 + lc * 2;
            float2 b0 = *(const float2*)(bias + c);
            float v0 = acc[mi][ni][0] + b0.x, v1 = acc[mi][ni][1] + b0.y;
            float v2 = acc[mi][ni][2] + b0.x, v3 = acc[mi][ni][3] + b0.y;
            if (OUTH) {
                __half* C = (__half*)go.out[buf];
                *(__half2*)(C + (size_t)r * DMODEL + c) =
                    __floats2half2_rn(v0 * oscale, v1 * oscale);
                *(__half2*)(C + (size_t)(r + 8) * DMODEL + c) =
                    __floats2half2_rn(v2 * oscale, v3 * oscale);
            } else {
                float* C = (float*)go.out[buf];
                *(float2*)(C + (size_t)r * DMODEL + c)       = make_float2(v0, v1);
                *(float2*)(C + (size_t)(r + 8) * DMODEL + c) = make_float2(v2, v3);
            }
        }
    }
}

// ---------------------------------------------------------------------------
// fp16 flash attention (causal): 64 q-rows/block, 4 warps (16 rows each),
// 64-key tiles, ldmatrix + 2-slot cp.async ring (one sync/iter),
// exp2-domain softmax. Q arrives pre-scaled by log2(e)/8.
// Smem = Q + P + 2K + 2V = 54 KB -> 4 blocks/SM.
// ---------------------------------------------------------------------------
#define RS 72
#define ATT_TILE (64 * RS)                       // halves per tile
#define ATT_SMEM ((2 + 4) * ATT_TILE * 2)        // 55296 bytes

__device__ __forceinline__ void att_copy_kv(
    uint32_t kdst, uint32_t vdst,
    const __half* Kp, const __half* Vp, int kt, int tid)
{
    #pragma unroll
    for (int j = 0; j < 4; j++) {
        const int i   = tid + j * 128;
        const int row = i >> 3;
        const int c8  = (i & 7) * 8;
        const size_t g = (size_t)(kt * 64 + row) * DMODEL + c8;
        cp16(kdst + (row * RS + c8) * 2, Kp + g);
        cp16(vdst + (row * RS + c8) * 2, Vp + g);
    }
}

__global__ __launch_bounds__(128) void flash_attn_h_kernel(
    const __half* __restrict__ Q, const __half* __restrict__ K,
    const __half* __restrict__ V, __half* __restrict__ Oh, int T)
{
    extern __shared__ __half hsm[];
    __half* Qs = hsm;
    __half* Ps = Qs + ATT_TILE;
    __half* Ks = Ps + ATT_TILE;           // 2 tiles
    __half* Vs = Ks + 2 * ATT_TILE;       // 2 tiles

    const int tid  = threadIdx.x;
    const int lane = tid & 31;
    const int warp = tid >> 5;
    const int lr   = lane >> 2;
    const int lc   = lane & 3;
    const int qt   = blockIdx.x;
    const int h    = blockIdx.y;
    const int bb   = blockIdx.z;

    const size_t base = ((size_t)bb * T) * DMODEL + h * DHEAD;
    const __half* Qp = Q + base;
    const __half* Kp = K + base;
    const __half* Vp = V + base;

    const uint32_t qb = smem_u32(Qs);
    const uint32_t kb = smem_u32(Ks);
    const uint32_t vb = smem_u32(Vs);
    const uint32_t pb = smem_u32(Ps);

    const int sel = lane >> 3, l7 = lane & 7;
    const uint32_t a_off = (((uint32_t)(warp * 16 + l7 + (sel & 1) * 8)) * RS
                            + (sel >> 1) * 8) * 2;
    const uint32_t kb_off = (((uint32_t)((sel >> 1) * 8 + l7)) * RS + (sel & 1) * 8) * 2;
    const uint32_t vb_off = (((uint32_t)((sel & 1) * 8 + l7)) * RS + (sel >> 1) * 8) * 2;

    const int nkt = qt + 1;

    // Prologue: prefetch tile 0 into slot 0
    att_copy_kv(kb, vb, Kp, Vp, 0, tid);
    cp_commit();

    // Load Q tile (fp16, pre-scaled by log2e/8 at projection)
    #pragma unroll
    for (int j = 0; j < 4; j++) {
        const int i   = tid + j * 128;
        const int row = i >> 3;
        const int c8  = (i & 7) * 8;
        *(uint4*)(Qs + row * RS + c8) =
            *(const uint4*)(Qp + (size_t)(qt * 64 + row) * DMODEL + c8);
    }

    float m0 = -INFINITY, m1 = -INFINITY, l0 = 0.f, l1 = 0.f;
    float o[8][4] = {};

    for (int kt = 0; kt < nkt; kt++) {
        cp_wait<0>();        // tile kt's group is the only one outstanding
        __syncthreads();     // publishes slot kt&1; proves iter kt-1 reads done

        // Prefetch kt+1 into slot (kt+1)&1 (its readers finished pre-sync)
        if (kt + 1 < nkt) {
            const int s1 = (kt + 1) & 1;
            att_copy_kv(kb + s1 * ATT_TILE * 2, vb + s1 * ATT_TILE * 2,
                        Kp, Vp, kt + 1, tid);
            cp_commit();
        }

        const uint32_t kcur = kb + (kt & 1) * ATT_TILE * 2;
        const uint32_t vcur = vb + (kt & 1) * ATT_TILE * 2;

        // S = Q K^T
        float s[8][4] = {};
        #pragma unroll
        for (int ks = 0; ks < 4; ks++) {
            unsigned a0, a1, a2, a3;
            ldsm_x4(a0, a1, a2, a3, qb + a_off + ks * 32);
            #pragma unroll
            for (int np = 0; np < 4; np++) {
                unsigned b0, b1, b2, b3;
                ldsm_x4(b0, b1, b2, b3,
                        kcur + kb_off + ((np * 16) * RS + ks * 16) * 2);
                mma_f16(s[2 * np][0], s[2 * np][1], s[2 * np][2], s[2 * np][3],
                        a0, a1, a2, a3, b0, b1);
                mma_f16(s[2 * np + 1][0], s[2 * np + 1][1],
                        s[2 * np + 1][2], s[2 * np + 1][3],
                        a0, a1, a2, a3, b2, b3);
            }
        }

        // Causal mask on diagonal tile
        if (kt == qt) {
            #pragma unroll
            for (int nt = 0; nt < 8; nt++) {
                const int col = nt * 8 + 2 * lc;
                const int r0l = warp * 16 + lr;
                if (col     > r0l)     s[nt][0] = -INFINITY;
                if (col + 1 > r0l)     s[nt][1] = -INFINITY;
                if (col     > r0l + 8) s[nt][2] = -INFINITY;
                if (col + 1 > r0l + 8) s[nt][3] = -INFINITY;
            }
        }

        // Online softmax in exp2 domain
        float mt0 = -INFINITY, mt1 = -INFINITY;
        #pragma unroll
        for (int nt = 0; nt < 8; nt++) {
            mt0 = fmaxf(mt0, fmaxf(s[nt][0], s[nt][1]));
            mt1 = fmaxf(mt1, fmaxf(s[nt][2], s[nt][3]));
        }
        #pragma unroll
        for (int off = 1; off <= 2; off <<= 1) {
            mt0 = fmaxf(mt0, __shfl_xor_sync(0xffffffffu, mt0, off));
            mt1 = fmaxf(mt1, __shfl_xor_sync(0xffffffffu, mt1, off));
        }
        const float mn0 = fmaxf(m0, mt0), mn1 = fmaxf(m1, mt1);
        const float corr0 = fexp2(m0 - mn0), corr1 = fexp2(m1 - mn1);
        float ls0 = 0.f, ls1 = 0.f;
        #pragma unroll
        for (int nt = 0; nt < 8; nt++) {
            s[nt][0] = fexp2(s[nt][0] - mn0);
            s[nt][1] = fexp2(s[nt][1] - mn0);
            s[nt][2] = fexp2(s[nt][2] - mn1);
            s[nt][3] = fexp2(s[nt][3] - mn1);
            ls0 += s[nt][0] + s[nt][1];
            ls1 += s[nt][2] + s[nt][3];
        }
        #pragma unroll
        for (int off = 1; off <= 2; off <<= 1) {
            ls0 += __shfl_xor_sync(0xffffffffu, ls0, off);
            ls1 += __shfl_xor_sync(0xffffffffu, ls1, off);
        }
        l0 = l0 * corr0 + ls0;  m0 = mn0;
        l1 = l1 * corr1 + ls1;  m1 = mn1;

        // Store P (fp16) to own warp stripe; rescale O
        {
            const uint32_t pr0 = (uint32_t)(warp * 16 + lr) * RS + 2 * lc;
            #pragma unroll
            for (int nt = 0; nt < 8; nt++) {
                o[nt][0] *= corr0; o[nt][1] *= corr0;
                o[nt][2] *= corr1; o[nt][3] *= corr1;
                *(__half2*)(Ps + pr0 + nt * 8) = __floats2half2_rn(s[nt][0], s[nt][1]);
                *(__half2*)(Ps + pr0 + 8 * RS + nt * 8) =
                    __floats2half2_rn(s[nt][2], s[nt][3]);
            }
        }
        __syncwarp();

        // O += P V
        #pragma unroll
        for (int ks = 0; ks < 4; ks++) {
            unsigned a0, a1, a2, a3;
            ldsm_x4(a0, a1, a2, a3, pb + a_off + ks * 32);
            #pragma unroll
            for (int np = 0; np < 4; np++) {
                unsigned b0, b1, b2, b3;
                ldsm_x4_t(b0, b1, b2, b3,
                          vcur + vb_off + ((ks * 16) * RS + np * 16) * 2);
                mma_f16(o[2 * np][0], o[2 * np][1], o[2 * np][2], o[2 * np][3],
                        a0, a1, a2, a3, b0, b1);
                mma_f16(o[2 * np + 1][0], o[2 * np + 1][1],
                        o[2 * np + 1][2], o[2 * np + 1][3],
                        a0, a1, a2, a3, b2, b3);
            }
        }
        // next iteration's __syncthreads covers WAR safety
    }

    // Epilogue: normalize + store fp16
    const float inv0 = 1.0f / l0, inv1 = 1.0f / l1;
    const size_t row0 = (size_t)bb * T + qt * 64 + warp * 16 + lr;
    #pragma unroll
    for (int nt = 0; nt < 8; nt++) {
        const int col = h * DHEAD + nt * 8 + 2 * lc;
        *(__half2*)(Oh + row0 * DMODEL + col) =
            __floats2half2_rn(o[nt][0] * inv0, o[nt][1] * inv0);
        *(__half2*)(Oh + (row0 + 8) * DMODEL + col) =
            __floats2half2_rn(o[nt][2] * inv1, o[nt][3] * inv1);
    }
}

// ---------------------------------------------------------------------------
extern "C" void kernel_launch(void* const* d_in, const int* in_sizes, int n_in,
                              void* d_out, int out_size)
{
    const float* x  = (const float*)d_in[0];
    const float* Wq = (const float*)d_in[1];
    const float* bq = (const float*)d_in[2];
    const float* Wk = (const float*)d_in[3];
    const float* bk = (const float*)d_in[4];
    const float* Wv = (const float*)d_in[5];
    const float* bv = (const float*)d_in[6];
    const float* Wo = (const float*)d_in[7];
    const float* bo = (const float*)d_in[8];
    float* out = (float*)d_out;

    const int M = in_sizes[0] / DMODEL;   // B*T
    const int B = M / TSEQ;

    __half *qh, *kh, *vh, *xh, *wh, *ah;
    cudaGetSymbolAddress((void**)&qh, g_Qh);
    cudaGetSymbolAddress((void**)&kh, g_Kh);
    cudaGetSymbolAddress((void**)&vh, g_Vh);
    cudaGetSymbolAddress((void**)&xh, g_xh);
    cudaGetSymbolAddress((void**)&wh, g_wh);
    cudaGetSymbolAddress((void**)&ah, g_ah);

    static bool attr_done = false;
    if (!attr_done) {
        cudaFuncSetAttribute(gemm_f16_kernel<0>,
                             cudaFuncAttributeMaxDynamicSharedMemorySize, GEMM_SMEM);
        cudaFuncSetAttribute(gemm_f16_kernel<1>,
                             cudaFuncAttributeMaxDynamicSharedMemorySize, GEMM_SMEM);
        cudaFuncSetAttribute(flash_attn_h_kernel,
                             cudaFuncAttributeMaxDynamicSharedMemorySize, ATT_SMEM);
        attr_done = true;
    }

    // 1. converts: x -> fp16; all 4 weights -> fp16 (one launch)
    const int xn4 = M * DMODEL / 4;
    const int wn4 = DMODEL * DMODEL / 4;
    tohalf_kernel<<<(xn4 + 255) / 256, 256>>>(x, xh, xn4);
    tohalf4_kernel<<<dim3((wn4 + 255) / 256, 4), 256>>>(Wq, Wk, Wv, Wo, wh, wn4);

    // 2. fused Q/K/V projection (Q pre-scaled by log2e/8 for exp2 softmax)
    GemmOuts qkv;
    qkv.out[0] = qh;  qkv.out[1] = kh;  qkv.out[2] = vh;
    qkv.bias[0] = bq; qkv.bias[1] = bk; qkv.bias[2] = bv;
    qkv.scale[0] = 0.125f * 1.44269504f; qkv.scale[1] = 1.0f; qkv.scale[2] = 1.0f;
    dim3 qgrid(3 * DMODEL / GBN, M / GBM);
    gemm_f16_kernel<1><<<qgrid, 256, GEMM_SMEM>>>(xh, wh, qkv);

    // 3. attention (64 q-rows/block, 2-slot cp.async ring; writes fp16)
    dim3 fgrid(TSEQ / 64, NHEADS, B);
    flash_attn_h_kernel<<<fgrid, 128, ATT_SMEM>>>(qh, kh, vh, ah, TSEQ);

    // 4. output projection (fp32 epilogue)
    GemmOuts og;
    og.out[0] = out; og.out[1] = out; og.out[2] = out;
    og.bias[0] = bo; og.bias[1] = bo; og.bias[2] = bo;
    og.scale[0] = 1.0f; og.scale[1] = 1.0f; og.scale[2] = 1.0f;
    dim3 ogrid(DMODEL / GBN, M / GBM);
    gemm_f16_kernel<0><<<ogrid, 256, GEMM_SMEM>>>(
        ah, wh + 3 * (size_t)DMODEL * DMODEL, og);
}

// round 16
// speedup vs baseline: 1.0863x; 1.0415x over previous
#include <cuda_runtime.h>
#include <cuda_fp16.h>
#include <math.h>
#include <stdint.h>

#define DMODEL 1024
#define NHEADS 16
#define DHEAD  64
#define TSEQ   2048
#define MMAX   4096   // B*T

// ---------------- device scratch (allocation-free) ----------------
__device__ __half g_Qh[MMAX * DMODEL];
__device__ __half g_Kh[MMAX * DMODEL];
__device__ __half g_Vh[MMAX * DMODEL];
__device__ __half g_xh[MMAX * DMODEL];
__device__ __half g_wh[4 * DMODEL * DMODEL];
__device__ __half g_ah[MMAX * DMODEL];

// ---------------- helpers ----------------
__device__ __forceinline__ void mma_f16(
    float& c0, float& c1, float& c2, float& c3,
    unsigned a0, unsigned a1, unsigned a2, unsigned a3,
    unsigned b0, unsigned b1)
{
    asm volatile(
        "mma.sync.aligned.m16n8k16.row.col.f32.f16.f16.f32 "
        "{%0,%1,%2,%3}, {%4,%5,%6,%7}, {%8,%9}, {%0,%1,%2,%3};\n"
        : "+f"(c0), "+f"(c1), "+f"(c2), "+f"(c3)
        : "r"(a0), "r"(a1), "r"(a2), "r"(a3), "r"(b0), "r"(b1));
}

__device__ __forceinline__ void ldsm_x4(
    unsigned& r0, unsigned& r1, unsigned& r2, unsigned& r3, uint32_t addr)
{
    asm volatile("ldmatrix.sync.aligned.m8n8.x4.shared.b16 {%0,%1,%2,%3}, [%4];"
                 : "=r"(r0), "=r"(r1), "=r"(r2), "=r"(r3) : "r"(addr));
}

__device__ __forceinline__ void ldsm_x4_t(
    unsigned& r0, unsigned& r1, unsigned& r2, unsigned& r3, uint32_t addr)
{
    asm volatile("ldmatrix.sync.aligned.m8n8.x4.trans.shared.b16 {%0,%1,%2,%3}, [%4];"
                 : "=r"(r0), "=r"(r1), "=r"(r2), "=r"(r3) : "r"(addr));
}

__device__ __forceinline__ float fexp2(float x) {
    float r;
    asm("ex2.approx.ftz.f32 %0, %1;" : "=f"(r) : "f"(x));
    return r;
}

__device__ __forceinline__ unsigned packh2(float a, float b) {
    __half2 h = __floats2half2_rn(a, b);
    return *reinterpret_cast<unsigned*>(&h);
}

__device__ __forceinline__ uint32_t smem_u32(const void* p) {
    uint32_t a;
    asm("{ .reg .u64 t; cvta.to.shared.u64 t, %1; cvt.u32.u64 %0, t; }"
        : "=r"(a) : "l"(p));
    return a;
}

__device__ __forceinline__ void cp16(uint32_t dst, const void* src) {
    asm volatile("cp.async.cg.shared.global [%0], [%1], 16;"
                 :: "r"(dst), "l"(src) : "memory");
}
__device__ __forceinline__ void cp_commit() {
    asm volatile("cp.async.commit_group;" ::: "memory");
}
template<int N> __device__ __forceinline__ void cp_wait() {
    asm volatile("cp.async.wait_group %0;" :: "n"(N) : "memory");
}

// ---------------------------------------------------------------------------
// Elementwise converts
// ---------------------------------------------------------------------------
__global__ __launch_bounds__(256) void tohalf_kernel(
    const float* __restrict__ in, __half* __restrict__ out, int n4)
{
    int i = blockIdx.x * blockDim.x + threadIdx.x;
    if (i >= n4) return;
    float4 v = ((const float4*)in)[i];
    __half2 a = __floats2half2_rn(v.x, v.y);
    __half2 b = __floats2half2_rn(v.z, v.w);
    ((uint2*)out)[i] = make_uint2(*reinterpret_cast<unsigned*>(&a),
                                  *reinterpret_cast<unsigned*>(&b));
}

// All four weights in one launch (blockIdx.y selects).
__global__ __launch_bounds__(256) void tohalf4_kernel(
    const float* __restrict__ w0, const float* __restrict__ w1,
    const float* __restrict__ w2, const float* __restrict__ w3,
    __half* __restrict__ out, int n4)
{
    const float* srcs[4] = {w0, w1, w2, w3};
    const float* in = srcs[blockIdx.y];
    __half* o = out + (size_t)blockIdx.y * DMODEL * DMODEL;
    int i = blockIdx.x * blockDim.x + threadIdx.x;
    if (i >= n4) return;
    float4 v = ((const float4*)in)[i];
    __half2 a = __floats2half2_rn(v.x, v.y);
    __half2 b = __floats2half2_rn(v.z, v.w);
    ((uint2*)o)[i] = make_uint2(*reinterpret_cast<unsigned*>(&a),
                                *reinterpret_cast<unsigned*>(&b));
}

// ---------------------------------------------------------------------------
// Single-term fp16 GEMM: C = Ah @ Wh^T + bias (f32 accum).
// BM=128, BN=128, BK=32, 256 threads = 8 warps (4Mx2N), warp tile 32x64.
// Multi-output: bn_global >> 10 selects out/bias/scale (QKV fused launch).
// ---------------------------------------------------------------------------
#define GBM 128
#define GBN 128
#define GBK 32
#define GST 20
#define TILE_U32 (128 * GST)
#define STAGE_U32 (2 * TILE_U32)      // Ah, Bh
#define GEMM_SMEM (2 * STAGE_U32 * 4)
#define NT (DMODEL / GBK)

struct GemmOuts {
    void* out[3];
    const float* bias[3];
    float scale[3];
};

__device__ __forceinline__ void gemm_copy_stage(
    uint32_t sbase, const __half* Ah, const __half* Bh,
    int bm, int bnG, int k0, int tid)
{
    const __half* srcs[2] = {Ah, Bh};
    #pragma unroll
    for (int t = 0; t < 2; t++) {
        const int rbase = (t == 0) ? bm : bnG;
        const uint32_t toff = sbase + t * TILE_U32 * 4;
        #pragma unroll
        for (int i = 0; i < 2; i++) {
            const int c   = tid + i * 256;
            const int row = c >> 2;
            const int kc  = c & 3;
            cp16(toff + (row * GST + kc * 4) * 4,
                 srcs[t] + (size_t)(rbase + row) * DMODEL + k0 + kc * 8);
        }
    }
}

template<int OUTH>
__global__ __launch_bounds__(256) void gemm_f16_kernel(
    const __half* __restrict__ Ah, const __half* __restrict__ Bh, GemmOuts go)
{
    extern __shared__ unsigned gsm[];
    const uint32_t sb = smem_u32(gsm);

    const int tid  = threadIdx.x;
    const int lane = tid & 31;
    const int warp = tid >> 5;
    const int wm   = warp >> 1;
    const int wn   = warp & 1;
    const int lr   = lane >> 2;
    const int lc   = lane & 3;

    const int bm  = blockIdx.y * GBM;
    const int bnG = blockIdx.x * GBN;
    const int buf = bnG >> 10;
    const int bn  = bnG & 1023;

    float acc[2][8][4] = {};

    gemm_copy_stage(sb, Ah, Bh, bm, bnG, 0, tid);
    cp_commit();

    for (int kt = 0; kt < NT; kt++) {
        const int cur = kt & 1;
        if (kt + 1 < NT) {
            gemm_copy_stage(sb + ((kt + 1) & 1) * STAGE_U32 * 4,
                            Ah, Bh, bm, bnG, (kt + 1) * GBK, tid);
            cp_commit();
            cp_wait<1>();
        } else {
            cp_wait<0>();
        }
        __syncthreads();

        const unsigned* As = gsm + cur * STAGE_U32;
        const unsigned* Bs = As + TILE_U32;

        #pragma unroll
        for (int ks = 0; ks < 2; ks++) {
            const int k = ks * 8;
            unsigned ah[2][4], bh[8][2];
            #pragma unroll
            for (int mi = 0; mi < 2; mi++) {
                const int r0 = (wm * 32 + mi * 16 + lr) * GST;
                ah[mi][0] = As[r0 + k + lc];
                ah[mi][1] = As[r0 + 8 * GST + k + lc];
                ah[mi][2] = As[r0 + k + lc + 4];
                ah[mi][3] = As[r0 + 8 * GST + k + lc + 4];
            }
            #pragma unroll
            for (int ni = 0; ni < 8; ni++) {
                const int n0 = (wn * 64 + ni * 8 + lr) * GST;
                bh[ni][0] = Bs[n0 + k + lc];
                bh[ni][1] = Bs[n0 + k + lc + 4];
            }
            #pragma unroll
            for (int mi = 0; mi < 2; mi++)
                #pragma unroll
                for (int ni = 0; ni < 8; ni++)
                    mma_f16(acc[mi][ni][0], acc[mi][ni][1],
                            acc[mi][ni][2], acc[mi][ni][3],
                            ah[mi][0], ah[mi][1], ah[mi][2], ah[mi][3],
                            bh[ni][0], bh[ni][1]);
        }
        __syncthreads();
    }

    const float* bias = go.bias[buf];
    const float oscale = go.scale[buf];

    #pragma unroll
    for (int mi = 0; mi < 2; mi++) {
        #pragma unroll
        for (int ni = 0; ni < 8; ni++) {
            const int r = bm + wm * 32 + mi * 16 + lr;
            const int c = bn + wn * 64 + ni * 8 + lc * 2;
            float2 b0 = *(const float2*)(bias + c);
            float v0 = acc[mi][ni][0] + b0.x, v1 = acc[mi][ni][1] + b0.y;
            float v2 = acc[mi][ni][2] + b0.x, v3 = acc[mi][ni][3] + b0.y;
            if (OUTH) {
                __half* C = (__half*)go.out[buf];
                *(__half2*)(C + (size_t)r * DMODEL + c) =
                    __floats2half2_rn(v0 * oscale, v1 * oscale);
                *(__half2*)(C + (size_t)(r + 8) * DMODEL + c) =
                    __floats2half2_rn(v2 * oscale, v3 * oscale);
            } else {
                float* C = (float*)go.out[buf];
                *(float2*)(C + (size_t)r * DMODEL + c)       = make_float2(v0, v1);
                *(float2*)(C + (size_t)(r + 8) * DMODEL + c) = make_float2(v2, v3);
            }
        }
    }
}

// ---------------------------------------------------------------------------
// fp16 flash attention (causal): 64 q-rows/block, 4 warps (16 rows each),
// 64-key tiles, 2-slot cp.async ring, exp2-domain softmax.
// P kept in registers: S accum fragment repacked directly into PV A-fragment
// (no smem round-trip). Q fragments hoisted out of the kv loop.
// Smem = Q + 2K + 2V = 46 KB.
// ---------------------------------------------------------------------------
#define RS 72
#define ATT_TILE (64 * RS)                       // halves per tile
#define ATT_SMEM ((1 + 4) * ATT_TILE * 2)        // 46080 bytes

__device__ __forceinline__ void att_copy_kv(
    uint32_t kdst, uint32_t vdst,
    const __half* Kp, const __half* Vp, int kt, int tid)
{
    #pragma unroll
    for (int j = 0; j < 4; j++) {
        const int i   = tid + j * 128;
        const int row = i >> 3;
        const int c8  = (i & 7) * 8;
        const size_t g = (size_t)(kt * 64 + row) * DMODEL + c8;
        cp16(kdst + (row * RS + c8) * 2, Kp + g);
        cp16(vdst + (row * RS + c8) * 2, Vp + g);
    }
}

__global__ __launch_bounds__(128) void flash_attn_h_kernel(
    const __half* __restrict__ Q, const __half* __restrict__ K,
    const __half* __restrict__ V, __half* __restrict__ Oh, int T)
{
    extern __shared__ __half hsm[];
    __half* Qs = hsm;
    __half* Ks = Qs + ATT_TILE;           // 2 tiles
    __half* Vs = Ks + 2 * ATT_TILE;       // 2 tiles

    const int tid  = threadIdx.x;
    const int lane = tid & 31;
    const int warp = tid >> 5;
    const int lr   = lane >> 2;
    const int lc   = lane & 3;
    const int qt   = blockIdx.x;
    const int h    = blockIdx.y;
    const int bb   = blockIdx.z;

    const size_t base = ((size_t)bb * T) * DMODEL + h * DHEAD;
    const __half* Qp = Q + base;
    const __half* Kp = K + base;
    const __half* Vp = V + base;

    const uint32_t qb = smem_u32(Qs);
    const uint32_t kb = smem_u32(Ks);
    const uint32_t vb = smem_u32(Vs);

    const int sel = lane >> 3, l7 = lane & 7;
    const uint32_t a_off = (((uint32_t)(warp * 16 + l7 + (sel & 1) * 8)) * RS
                            + (sel >> 1) * 8) * 2;
    const uint32_t kb_off = (((uint32_t)((sel >> 1) * 8 + l7)) * RS + (sel & 1) * 8) * 2;
    const uint32_t vb_off = (((uint32_t)((sel & 1) * 8 + l7)) * RS + (sel >> 1) * 8) * 2;

    const int nkt = qt + 1;

    // Prologue: prefetch tile 0 into slot 0
    att_copy_kv(kb, vb, Kp, Vp, 0, tid);
    cp_commit();

    // Load Q tile (fp16, pre-scaled by log2e/8 at projection)
    #pragma unroll
    for (int j = 0; j < 4; j++) {
        const int i   = tid + j * 128;
        const int row = i >> 3;
        const int c8  = (i & 7) * 8;
        *(uint4*)(Qs + row * RS + c8) =
            *(const uint4*)(Qp + (size_t)(qt * 64 + row) * DMODEL + c8);
    }
    __syncthreads();

    // Hoist Q fragments into registers (loop-invariant)
    unsigned qa[4][4];
    #pragma unroll
    for (int ks = 0; ks < 4; ks++)
        ldsm_x4(qa[ks][0], qa[ks][1], qa[ks][2], qa[ks][3],
                qb + a_off + ks * 32);

    float m0 = -INFINITY, m1 = -INFINITY, l0 = 0.f, l1 = 0.f;
    float o[8][4] = {};

    for (int kt = 0; kt < nkt; kt++) {
        cp_wait<0>();        // tile kt's group is the only one outstanding
        __syncthreads();     // publishes slot kt&1; proves iter kt-1 reads done

        // Prefetch kt+1 into slot (kt+1)&1 (its readers finished pre-sync)
        if (kt + 1 < nkt) {
            const int s1 = (kt + 1) & 1;
            att_copy_kv(kb + s1 * ATT_TILE * 2, vb + s1 * ATT_TILE * 2,
                        Kp, Vp, kt + 1, tid);
            cp_commit();
        }

        const uint32_t kcur = kb + (kt & 1) * ATT_TILE * 2;
        const uint32_t vcur = vb + (kt & 1) * ATT_TILE * 2;

        // S = Q K^T
        float s[8][4] = {};
        #pragma unroll
        for (int ks = 0; ks < 4; ks++) {
            #pragma unroll
            for (int np = 0; np < 4; np++) {
                unsigned b0, b1, b2, b3;
                ldsm_x4(b0, b1, b2, b3,
                        kcur + kb_off + ((np * 16) * RS + ks * 16) * 2);
                mma_f16(s[2 * np][0], s[2 * np][1], s[2 * np][2], s[2 * np][3],
                        qa[ks][0], qa[ks][1], qa[ks][2], qa[ks][3], b0, b1);
                mma_f16(s[2 * np + 1][0], s[2 * np + 1][1],
                        s[2 * np + 1][2], s[2 * np + 1][3],
                        qa[ks][0], qa[ks][1], qa[ks][2], qa[ks][3], b2, b3);
            }
        }

        // Causal mask on diagonal tile
        if (kt == qt) {
            #pragma unroll
            for (int nt = 0; nt < 8; nt++) {
                const int col = nt * 8 + 2 * lc;
                const int r0l = warp * 16 + lr;
                if (col     > r0l)     s[nt][0] = -INFINITY;
                if (col + 1 > r0l)     s[nt][1] = -INFINITY;
                if (col     > r0l + 8) s[nt][2] = -INFINITY;
                if (col + 1 > r0l + 8) s[nt][3] = -INFINITY;
            }
        }

        // Online softmax in exp2 domain
        float mt0 = -INFINITY, mt1 = -INFINITY;
        #pragma unroll
        for (int nt = 0; nt < 8; nt++) {
            mt0 = fmaxf(mt0, fmaxf(s[nt][0], s[nt][1]));
            mt1 = fmaxf(mt1, fmaxf(s[nt][2], s[nt][3]));
        }
        #pragma unroll
        for (int off = 1; off <= 2; off <<= 1) {
            mt0 = fmaxf(mt0, __shfl_xor_sync(0xffffffffu, mt0, off));
            mt1 = fmaxf(mt1, __shfl_xor_sync(0xffffffffu, mt1, off));
        }
        const float mn0 = fmaxf(m0, mt0), mn1 = fmaxf(m1, mt1);
        const float corr0 = fexp2(m0 - mn0), corr1 = fexp2(m1 - mn1);
        float ls0 = 0.f, ls1 = 0.f;
        #pragma unroll
        for (int nt = 0; nt < 8; nt++) {
            s[nt][0] = fexp2(s[nt][0] - mn0);
            s[nt][1] = fexp2(s[nt][1] - mn0);
            s[nt][2] = fexp2(s[nt][2] - mn1);
            s[nt][3] = fexp2(s[nt][3] - mn1);
            ls0 += s[nt][0] + s[nt][1];
            ls1 += s[nt][2] + s[nt][3];
        }
        #pragma unroll
        for (int off = 1; off <= 2; off <<= 1) {
            ls0 += __shfl_xor_sync(0xffffffffu, ls0, off);
            ls1 += __shfl_xor_sync(0xffffffffu, ls1, off);
        }
        l0 = l0 * corr0 + ls0;  m0 = mn0;
        l1 = l1 * corr1 + ls1;  m1 = mn1;

        // Rescale O
        #pragma unroll
        for (int nt = 0; nt < 8; nt++) {
            o[nt][0] *= corr0; o[nt][1] *= corr0;
            o[nt][2] *= corr1; o[nt][3] *= corr1;
        }

        // O += P V : P fragments packed directly from S registers
        #pragma unroll
        for (int ks = 0; ks < 4; ks++) {
            const unsigned pa0 = packh2(s[2 * ks][0], s[2 * ks][1]);
            const unsigned pa1 = packh2(s[2 * ks][2], s[2 * ks][3]);
            const unsigned pa2 = packh2(s[2 * ks + 1][0], s[2 * ks + 1][1]);
            const unsigned pa3 = packh2(s[2 * ks + 1][2], s[2 * ks + 1][3]);
            #pragma unroll
            for (int np = 0; np < 4; np++) {
                unsigned b0, b1, b2, b3;
                ldsm_x4_t(b0, b1, b2, b3,
                          vcur + vb_off + ((ks * 16) * RS + np * 16) * 2);
                mma_f16(o[2 * np][0], o[2 * np][1], o[2 * np][2], o[2 * np][3],
                        pa0, pa1, pa2, pa3, b0, b1);
                mma_f16(o[2 * np + 1][0], o[2 * np + 1][1],
                        o[2 * np + 1][2], o[2 * np + 1][3],
                        pa0, pa1, pa2, pa3, b2, b3);
            }
        }
        // next iteration's __syncthreads covers WAR safety
    }

    // Epilogue: normalize + store fp16
    const float inv0 = 1.0f / l0, inv1 = 1.0f / l1;
    const size_t row0 = (size_t)bb * T + qt * 64 + warp * 16 + lr;
    #pragma unroll
    for (int nt = 0; nt < 8; nt++) {
        const int col = h * DHEAD + nt * 8 + 2 * lc;
        *(__half2*)(Oh + row0 * DMODEL + col) =
            __floats2half2_rn(o[nt][0] * inv0, o[nt][1] * inv0);
        *(__half2*)(Oh + (row0 + 8) * DMODEL + col) =
            __floats2half2_rn(o[nt][2] * inv1, o[nt][3] * inv1);
    }
}

// ---------------------------------------------------------------------------
extern "C" void kernel_launch(void* const* d_in, const int* in_sizes, int n_in,
                              void* d_out, int out_size)
{
    const float* x  = (const float*)d_in[0];
    const float* Wq = (const float*)d_in[1];
    const float* bq = (const float*)d_in[2];
    const float* Wk = (const float*)d_in[3];
    const float* bk = (const float*)d_in[4];
    const float* Wv = (const float*)d_in[5];
    const float* bv = (const float*)d_in[6];
    const float* Wo = (const float*)d_in[7];
    const float* bo = (const float*)d_in[8];
    float* out = (float*)d_out;

    const int M = in_sizes[0] / DMODEL;   // B*T
    const int B = M / TSEQ;

    __half *qh, *kh, *vh, *xh, *wh, *ah;
    cudaGetSymbolAddress((void**)&qh, g_Qh);
    cudaGetSymbolAddress((void**)&kh, g_Kh);
    cudaGetSymbolAddress((void**)&vh, g_Vh);
    cudaGetSymbolAddress((void**)&xh, g_xh);
    cudaGetSymbolAddress((void**)&wh, g_wh);
    cudaGetSymbolAddress((void**)&ah, g_ah);

    static bool attr_done = false;
    if (!attr_done) {
        cudaFuncSetAttribute(gemm_f16_kernel<0>,
                             cudaFuncAttributeMaxDynamicSharedMemorySize, GEMM_SMEM);
        cudaFuncSetAttribute(gemm_f16_kernel<1>,
                             cudaFuncAttributeMaxDynamicSharedMemorySize, GEMM_SMEM);
        cudaFuncSetAttribute(flash_attn_h_kernel,
                             cudaFuncAttributeMaxDynamicSharedMemorySize, ATT_SMEM);
        attr_done = true;
    }

    // 1. converts: x -> fp16; all 4 weights -> fp16 (one launch)
    const int xn4 = M * DMODEL / 4;
    const int wn4 = DMODEL * DMODEL / 4;
    tohalf_kernel<<<(xn4 + 255) / 256, 256>>>(x, xh, xn4);
    tohalf4_kernel<<<dim3((wn4 + 255) / 256, 4), 256>>>(Wq, Wk, Wv, Wo, wh, wn4);

    // 2. fused Q/K/V projection (Q pre-scaled by log2e/8 for exp2 softmax)
    GemmOuts qkv;
    qkv.out[0] = qh;  qkv.out[1] = kh;  qkv.out[2] = vh;
    qkv.bias[0] = bq; qkv.bias[1] = bk; qkv.bias[2] = bv;
    qkv.scale[0] = 0.125f * 1.44269504f; qkv.scale[1] = 1.0f; qkv.scale[2] = 1.0f;
    dim3 qgrid(3 * DMODEL / GBN, M / GBM);
    gemm_f16_kernel<1><<<qgrid, 256, GEMM_SMEM>>>(xh, wh, qkv);

    // 3. attention (64 q-rows/block, register-P, 2-slot ring; writes fp16)
    dim3 fgrid(TSEQ / 64, NHEADS, B);
    flash_attn_h_kernel<<<fgrid, 128, ATT_SMEM>>>(qh, kh, vh, ah, TSEQ);

    // 4. output projection (fp32 epilogue)
    GemmOuts og;
    og.out[0] = out; og.out[1] = out; og.out[2] = out;
    og.bias[0] = bo; og.bias[1] = bo; og.bias[2] = bo;
    og.scale[0] = 1.0f; og.scale[1] = 1.0f; og.scale[2] = 1.0f;
    dim3 ogrid(DMODEL / GBN, M / GBM);
    gemm_f16_kernel<0><<<ogrid, 256, GEMM_SMEM>>>(
        ah, wh + 3 * (size_t)DMODEL * DMODEL, og);
}